// round 6
// baseline (speedup 1.0000x reference)
#include <cuda_runtime.h>

// Causal FlashAttention fp32, SIMT f32x2 FMA, 8x8 register blocking (sm_103a).
// 128x128 tiles, K/V time-share one smem buffer. Online softmax in registers.

#define BR 128
#define BC 128
#define HD 128
#define PS_STRIDE 132   // 128 + 4 pad
#define NTHREADS 256
#define SCALE 0.08838834764831845f  // 1/sqrt(128)

typedef unsigned long long ull;

struct SmemLayout {
    float Qs[HD][BR];        // Q transposed (d-major), pre-scaled   64 KB
    float KV[HD * BC];       // K (d-major) OR V (row-major)         64 KB
    float Ps[BR][PS_STRIDE]; // probabilities                        66 KB
};

__device__ __forceinline__ ull dup2(float x) {
    ull r; unsigned u = __float_as_uint(x);
    asm("mov.b64 %0, {%1, %1};" : "=l"(r) : "r"(u));
    return r;
}
__device__ __forceinline__ void unpack2(ull p, float& lo, float& hi) {
    unsigned a, b;
    asm("mov.b64 {%0, %1}, %2;" : "=r"(a), "=r"(b) : "l"(p));
    lo = __uint_as_float(a); hi = __uint_as_float(b);
}
__device__ __forceinline__ ull ffma2(ull a, ull b, ull c) {
    ull d;
    asm("fma.rn.f32x2 %0, %1, %2, %3;" : "=l"(d) : "l"(a), "l"(b), "l"(c));
    return d;
}
__device__ __forceinline__ ull fmul2(ull a, ull b) {
    ull d;
    asm("mul.rn.f32x2 %0, %1, %2;" : "=l"(d) : "l"(a), "l"(b));
    return d;
}

__global__ __launch_bounds__(NTHREADS, 1)
void flash_fwd_kernel(const float* __restrict__ gq,
                      const float* __restrict__ gk,
                      const float* __restrict__ gv,
                      float* __restrict__ gout,
                      int seqlen)
{
    extern __shared__ char raw[];
    SmemLayout* sm = reinterpret_cast<SmemLayout*>(raw);

    const int tid = threadIdx.x;
    const int tx = tid & 15;        // 16 col groups: cols tx*8 .. tx*8+7
    const int ty = tid >> 4;        // 16 row groups: rows ty*8 .. ty*8+7
    const int bh = blockIdx.y;
    const int qtile = gridDim.x - 1 - blockIdx.x;   // heavy tiles first
    const int qbase = qtile * BR;
    const size_t bh_off = (size_t)bh * seqlen * HD;

    // ---- Load Q tile transposed (d-major), fold scale ----
    {
        int r = tid & 127;          // consecutive lanes -> consecutive rows: STS conflict-free
        int cg = tid >> 7;          // 2 chunk groups
        const float* qp = gq + bh_off + (size_t)(qbase + r) * HD;
        #pragma unroll
        for (int jj = 0; jj < 16; ++jj) {
            int c = cg + jj * 2;    // float4 chunk 0..31
            float4 t = *(const float4*)(qp + c * 4);
            sm->Qs[c * 4 + 0][r] = t.x * SCALE;
            sm->Qs[c * 4 + 1][r] = t.y * SCALE;
            sm->Qs[c * 4 + 2][r] = t.z * SCALE;
            sm->Qs[c * 4 + 3][r] = t.w * SCALE;
        }
    }

    // Per-thread state: 8 rows, 8 cols of O
    float m_r[8], l_r[8];
    ull acco[8][4];   // row r, col-pairs {8tx+0,1}{2,3}{4,5}{6,7}
    #pragma unroll
    for (int r = 0; r < 8; ++r) {
        m_r[r] = -1e30f; l_r[r] = 0.0f;
        #pragma unroll
        for (int c = 0; c < 4; ++c) acco[r][c] = 0ull;
    }

    for (int j = 0; j <= qtile; ++j) {
        const int kbase = j * BC;
        __syncthreads();   // prev-iter readers of KV(V)/Ps done before K overwrite

        // ---- K tile transposed (d-major) into KV ----
        float (*Ks)[BC] = reinterpret_cast<float (*)[BC]>(sm->KV);
        {
            int r = tid & 127;
            int cg = tid >> 7;
            const float* kp = gk + bh_off + (size_t)(kbase + r) * HD;
            #pragma unroll
            for (int jj = 0; jj < 16; ++jj) {
                int c = cg + jj * 2;
                float4 t = *(const float4*)(kp + c * 4);
                Ks[c * 4 + 0][r] = t.x;
                Ks[c * 4 + 1][r] = t.y;
                Ks[c * 4 + 2][r] = t.z;
                Ks[c * 4 + 3][r] = t.w;
            }
        }
        __syncthreads();

        // ---- S = Q @ K^T : 8x8 per thread, rows paired in f32x2 ----
        ull accs[4][8];   // row-pair rp = rows (2rp, 2rp+1), 8 cols
        #pragma unroll
        for (int rp = 0; rp < 4; ++rp)
            #pragma unroll
            for (int c = 0; c < 8; ++c) accs[rp][c] = 0ull;

        {
            const float* qcol = &sm->Qs[0][ty * 8];
            const float* kcol = &Ks[0][tx * 8];
            #pragma unroll 2
            for (int kk = 0; kk < HD; ++kk) {
                ulonglong2 a01 = *(const ulonglong2*)(qcol + kk * BR);     // rows 0-3
                ulonglong2 a23 = *(const ulonglong2*)(qcol + kk * BR + 4); // rows 4-7
                float4 b0 = *(const float4*)(kcol + kk * BC);
                float4 b1 = *(const float4*)(kcol + kk * BC + 4);
                ull bd[8];
                bd[0] = dup2(b0.x); bd[1] = dup2(b0.y);
                bd[2] = dup2(b0.z); bd[3] = dup2(b0.w);
                bd[4] = dup2(b1.x); bd[5] = dup2(b1.y);
                bd[6] = dup2(b1.z); bd[7] = dup2(b1.w);
                #pragma unroll
                for (int c = 0; c < 8; ++c) {
                    accs[0][c] = ffma2(a01.x, bd[c], accs[0][c]);
                    accs[1][c] = ffma2(a01.y, bd[c], accs[1][c]);
                    accs[2][c] = ffma2(a23.x, bd[c], accs[2][c]);
                    accs[3][c] = ffma2(a23.y, bd[c], accs[3][c]);
                }
            }
        }

        // ---- online softmax, row-pair at a time (caps live registers) ----
        const bool diag = (j == qtile);
        #pragma unroll
        for (int rp = 0; rp < 4; ++rp) {
            float v[2][8];
            #pragma unroll
            for (int c = 0; c < 8; ++c) unpack2(accs[rp][c], v[0][c], v[1][c]);

            #pragma unroll
            for (int h = 0; h < 2; ++h) {
                const int lr = rp * 2 + h;          // 0..7 local row in thread
                const int lrow = ty * 8 + lr;       // row within tile
                if (diag) {
                    #pragma unroll
                    for (int c = 0; c < 8; ++c)
                        if (tx * 8 + c > lrow) v[h][c] = -1e30f;
                }
                float mx = v[h][0];
                #pragma unroll
                for (int c = 1; c < 8; ++c) mx = fmaxf(mx, v[h][c]);
                #pragma unroll
                for (int off = 8; off >= 1; off >>= 1)
                    mx = fmaxf(mx, __shfl_xor_sync(0xffffffffu, mx, off));

                float mn = fmaxf(m_r[lr], mx);
                float fac = __expf(m_r[lr] - mn);
                m_r[lr] = mn;

                float p[8], rs = 0.0f;
                #pragma unroll
                for (int c = 0; c < 8; ++c) { p[c] = __expf(v[h][c] - mn); rs += p[c]; }
                #pragma unroll
                for (int off = 8; off >= 1; off >>= 1)
                    rs += __shfl_xor_sync(0xffffffffu, rs, off);
                l_r[lr] = l_r[lr] * fac + rs;

                *(float4*)&sm->Ps[lrow][tx * 8]     = make_float4(p[0], p[1], p[2], p[3]);
                *(float4*)&sm->Ps[lrow][tx * 8 + 4] = make_float4(p[4], p[5], p[6], p[7]);

                ull f2 = dup2(fac);
                #pragma unroll
                for (int cp = 0; cp < 4; ++cp) acco[lr][cp] = fmul2(acco[lr][cp], f2);
            }
        }
        __syncthreads();   // S-GEMM reads of KV(K) done; P visible

        // ---- V tile (row-major) into KV ----
        float (*Vs)[HD] = reinterpret_cast<float (*)[HD]>(sm->KV);
        {
            const float* vp = gv + bh_off + (size_t)kbase * HD;
            #pragma unroll
            for (int jj = 0; jj < 16; ++jj) {
                int idx = tid + jj * NTHREADS;      // float4 unit index 0..4095
                int rr = idx >> 5, cc = idx & 31;
                *(float4*)&Vs[rr][cc * 4] = *(const float4*)(vp + rr * HD + cc * 4);
            }
        }
        __syncthreads();

        // ---- O += P @ V : cols paired in f32x2 ----
        {
            const float* prow = &sm->Ps[ty * 8][0];
            #pragma unroll 2
            for (int kv = 0; kv < BC; ++kv) {
                float a[8];
                #pragma unroll
                for (int r = 0; r < 8; ++r) a[r] = prow[r * PS_STRIDE + kv];
                ulonglong2 b01 = *(const ulonglong2*)&Vs[kv][tx * 8];
                ulonglong2 b23 = *(const ulonglong2*)&Vs[kv][tx * 8 + 4];
                #pragma unroll
                for (int r = 0; r < 8; ++r) {
                    ull ad = dup2(a[r]);
                    acco[r][0] = ffma2(ad, b01.x, acco[r][0]);
                    acco[r][1] = ffma2(ad, b01.y, acco[r][1]);
                    acco[r][2] = ffma2(ad, b23.x, acco[r][2]);
                    acco[r][3] = ffma2(ad, b23.y, acco[r][3]);
                }
            }
        }
    }

    // ---- epilogue: O /= l, write out (contiguous 8 cols per thread) ----
    #pragma unroll
    for (int r = 0; r < 8; ++r) {
        float inv = 1.0f / l_r[r];
        float o[8];
        unpack2(acco[r][0], o[0], o[1]);
        unpack2(acco[r][1], o[2], o[3]);
        unpack2(acco[r][2], o[4], o[5]);
        unpack2(acco[r][3], o[6], o[7]);
        float* orow = gout + bh_off + (size_t)(qbase + ty * 8 + r) * HD + tx * 8;
        *(float4*)(orow)     = make_float4(o[0]*inv, o[1]*inv, o[2]*inv, o[3]*inv);
        *(float4*)(orow + 4) = make_float4(o[4]*inv, o[5]*inv, o[6]*inv, o[7]*inv);
    }
}

extern "C" void kernel_launch(void* const* d_in, const int* in_sizes, int n_in,
                              void* d_out, int out_size)
{
    const float* q = (const float*)d_in[0];
    const float* k = (const float*)d_in[1];
    const float* v = (const float*)d_in[2];
    float* out = (float*)d_out;

    const int seqlen = 2048;
    const int nbh = in_sizes[0] / (seqlen * HD);   // B*H = 32

    size_t smem = sizeof(SmemLayout);
    cudaFuncSetAttribute(flash_fwd_kernel,
                         cudaFuncAttributeMaxDynamicSharedMemorySize, (int)smem);

    dim3 grid(seqlen / BR, nbh);
    flash_fwd_kernel<<<grid, NTHREADS, smem>>>(q, k, v, out, seqlen);
}

// round 8
// speedup vs baseline: 1.8071x; 1.8071x over previous
#include <cuda_runtime.h>
#include <cuda_bf16.h>
#include <cstdint>

// Causal FlashAttention, fp32 accuracy via split-bf16 mma.sync (HMMA fallback,
// works on plain sm_103 PTX target). 128x128 tiles, 8 warps x 16 q-rows.
// x = hi + lo (bf16 each); x*y ~= hi*hi + hi*lo + lo*hi  (3 MMAs per GEMM).

#define HD 128
#define BT 128
#define STR 136                    // smem row stride in bf16 elems (272 B)
#define ROWB (STR * 2)             // 272 bytes per row
#define TILE_B (BT * ROWB)         // 34816 B per tile buffer
#define SQHI 0
#define SQLO (1 * TILE_B)
#define SKHI (2 * TILE_B)
#define SKLO (3 * TILE_B)
#define SVHI (4 * TILE_B)
#define SVLO (5 * TILE_B)
#define SM_TOTAL (6 * TILE_B)      // 208896 B
#define SCALE 0.08838834764831845f // 1/sqrt(128)

__device__ __forceinline__ uint32_t smem_u32(const void* p) {
    uint32_t a;
    asm("{ .reg .u64 t; cvta.to.shared.u64 t, %1; cvt.u32.u64 %0, t; }" : "=r"(a) : "l"(p));
    return a;
}

// split two floats into packed bf16x2 hi + bf16x2 lo (lo = exact residual rounded)
__device__ __forceinline__ void split2(float f0, float f1, uint32_t& hi, uint32_t& lo) {
    asm("cvt.rn.bf16x2.f32 %0, %1, %2;" : "=r"(hi) : "f"(f1), "f"(f0));
    float h0 = __uint_as_float(hi << 16);
    float h1 = __uint_as_float(hi & 0xFFFF0000u);
    float l0 = f0 - h0, l1 = f1 - h1;
    asm("cvt.rn.bf16x2.f32 %0, %1, %2;" : "=r"(lo) : "f"(l1), "f"(l0));
}

__device__ __forceinline__ void ldm4(uint32_t* r, uint32_t addr) {
    asm volatile("ldmatrix.sync.aligned.m8n8.x4.shared.b16 {%0,%1,%2,%3}, [%4];"
                 : "=r"(r[0]), "=r"(r[1]), "=r"(r[2]), "=r"(r[3]) : "r"(addr));
}
__device__ __forceinline__ void ldm4t(uint32_t* r, uint32_t addr) {
    asm volatile("ldmatrix.sync.aligned.m8n8.x4.trans.shared.b16 {%0,%1,%2,%3}, [%4];"
                 : "=r"(r[0]), "=r"(r[1]), "=r"(r[2]), "=r"(r[3]) : "r"(addr));
}
__device__ __forceinline__ void mma16816(float* c, const uint32_t* a,
                                         uint32_t b0, uint32_t b1) {
    asm volatile("mma.sync.aligned.m16n8k16.row.col.f32.bf16.bf16.f32 "
                 "{%0,%1,%2,%3}, {%4,%5,%6,%7}, {%8,%9}, {%0,%1,%2,%3};"
                 : "+f"(c[0]), "+f"(c[1]), "+f"(c[2]), "+f"(c[3])
                 : "r"(a[0]), "r"(a[1]), "r"(a[2]), "r"(a[3]), "r"(b0), "r"(b1));
}

__global__ __launch_bounds__(256, 1)
void fa_mma_kernel(const float* __restrict__ gq,
                   const float* __restrict__ gk,
                   const float* __restrict__ gv,
                   float* __restrict__ gout,
                   int seqlen)
{
    extern __shared__ char smem[];
    const uint32_t sb = smem_u32(smem);
    const int tid = threadIdx.x;
    const int lane = tid & 31;
    const int w = tid >> 5;                  // 8 warps, warp w owns rows 16w..16w+15
    const int bh = blockIdx.y;
    const int qtile = gridDim.x - 1 - blockIdx.x;   // heavy tiles first
    const int qbase = qtile * BT;
    const size_t bh_off = (size_t)bh * seqlen * HD;

    // ---- Q tile -> smem bf16 hi/lo, scale folded ----
    {
        const float* qp = gq + bh_off + (size_t)qbase * HD;
        #pragma unroll
        for (int it = 0; it < 16; ++it) {
            int idx = tid + it * 256;
            int r = idx >> 5, c4 = idx & 31;
            float4 t = *(const float4*)(qp + (size_t)r * HD + c4 * 4);
            uint32_t h01, l01, h23, l23;
            split2(t.x * SCALE, t.y * SCALE, h01, l01);
            split2(t.z * SCALE, t.w * SCALE, h23, l23);
            uint32_t off = (uint32_t)(r * ROWB + c4 * 8);
            *(uint2*)(smem + SQHI + off) = make_uint2(h01, h23);
            *(uint2*)(smem + SQLO + off) = make_uint2(l01, l23);
        }
    }

    const int rl0 = 16 * w + (lane >> 2);        // local row (low half); +8 = high half
    const uint32_t coladd = (lane & 16) ? 16u : 0u;          // +8 elems = 16 B
    const uint32_t arow_off = (uint32_t)((16 * w + (lane & 15)) * ROWB) + coladd;
    const uint32_t brow_off = (uint32_t)((lane & 15) * ROWB) + coladd;

    float m0 = -1e30f, m1 = -1e30f, l0 = 0.0f, l1 = 0.0f;
    float oa[16][4];
    #pragma unroll
    for (int t = 0; t < 16; ++t)
        #pragma unroll
        for (int e = 0; e < 4; ++e) oa[t][e] = 0.0f;

    for (int j = 0; j <= qtile; ++j) {
        const int kbase = j * BT;
        __syncthreads();   // prior-iter MMA reads of K/V smem done

        // ---- K and V tiles -> smem bf16 hi/lo (both row-major) ----
        {
            const float* kp = gk + bh_off + (size_t)kbase * HD;
            const float* vp = gv + bh_off + (size_t)kbase * HD;
            #pragma unroll
            for (int it = 0; it < 16; ++it) {
                int idx = tid + it * 256;
                int r = idx >> 5, c4 = idx & 31;
                uint32_t off = (uint32_t)(r * ROWB + c4 * 8);
                float4 tk = *(const float4*)(kp + (size_t)r * HD + c4 * 4);
                uint32_t h01, l01, h23, l23;
                split2(tk.x, tk.y, h01, l01);
                split2(tk.z, tk.w, h23, l23);
                *(uint2*)(smem + SKHI + off) = make_uint2(h01, h23);
                *(uint2*)(smem + SKLO + off) = make_uint2(l01, l23);
                float4 tv = *(const float4*)(vp + (size_t)r * HD + c4 * 4);
                split2(tv.x, tv.y, h01, l01);
                split2(tv.z, tv.w, h23, l23);
                *(uint2*)(smem + SVHI + off) = make_uint2(h01, h23);
                *(uint2*)(smem + SVLO + off) = make_uint2(l01, l23);
            }
        }
        __syncthreads();

        // ---- S = Q @ K^T (split-bf16, 3 MMAs per tile) ----
        float sa[16][4];
        #pragma unroll
        for (int t = 0; t < 16; ++t)
            #pragma unroll
            for (int e = 0; e < 4; ++e) sa[t][e] = 0.0f;

        #pragma unroll 2
        for (int s = 0; s < 8; ++s) {           // k16 step over d
            uint32_t ah[4], al[4];
            ldm4(ah, sb + SQHI + arow_off + s * 32);
            ldm4(al, sb + SQLO + arow_off + s * 32);
            #pragma unroll
            for (int t2 = 0; t2 < 8; ++t2) {    // n16 = two n8 tiles
                uint32_t bhh[4], bll[4];
                uint32_t baddr = sb + SKHI + (uint32_t)(t2 * 16 * ROWB) + brow_off + s * 32;
                ldm4(bhh, baddr);
                ldm4(bll, baddr + (SKLO - SKHI));
                // non-trans pairing: tile0={r0,r2}, tile1={r1,r3}
                mma16816(sa[2 * t2],     ah, bhh[0], bhh[2]);
                mma16816(sa[2 * t2],     ah, bll[0], bll[2]);
                mma16816(sa[2 * t2],     al, bhh[0], bhh[2]);
                mma16816(sa[2 * t2 + 1], ah, bhh[1], bhh[3]);
                mma16816(sa[2 * t2 + 1], ah, bll[1], bll[3]);
                mma16816(sa[2 * t2 + 1], al, bhh[1], bhh[3]);
            }
        }

        // ---- causal mask on diagonal tile ----
        if (j == qtile) {
            #pragma unroll
            for (int t = 0; t < 16; ++t) {
                int c = 8 * t + 2 * (lane & 3);
                if (c     > rl0)     sa[t][0] = -1e30f;
                if (c + 1 > rl0)     sa[t][1] = -1e30f;
                if (c     > rl0 + 8) sa[t][2] = -1e30f;
                if (c + 1 > rl0 + 8) sa[t][3] = -1e30f;
            }
        }

        // ---- online softmax (two rows per thread; reduce over 4 lanes) ----
        float mx0 = -1e30f, mx1 = -1e30f;
        #pragma unroll
        for (int t = 0; t < 16; ++t) {
            mx0 = fmaxf(mx0, fmaxf(sa[t][0], sa[t][1]));
            mx1 = fmaxf(mx1, fmaxf(sa[t][2], sa[t][3]));
        }
        mx0 = fmaxf(mx0, __shfl_xor_sync(0xffffffffu, mx0, 1));
        mx0 = fmaxf(mx0, __shfl_xor_sync(0xffffffffu, mx0, 2));
        mx1 = fmaxf(mx1, __shfl_xor_sync(0xffffffffu, mx1, 1));
        mx1 = fmaxf(mx1, __shfl_xor_sync(0xffffffffu, mx1, 2));

        float mn0 = fmaxf(m0, mx0), mn1 = fmaxf(m1, mx1);
        float f0 = __expf(m0 - mn0), f1 = __expf(m1 - mn1);
        m0 = mn0; m1 = mn1;

        float s0 = 0.0f, s1 = 0.0f;
        #pragma unroll
        for (int t = 0; t < 16; ++t) {
            sa[t][0] = __expf(sa[t][0] - mn0);
            sa[t][1] = __expf(sa[t][1] - mn0);
            sa[t][2] = __expf(sa[t][2] - mn1);
            sa[t][3] = __expf(sa[t][3] - mn1);
            s0 += sa[t][0] + sa[t][1];
            s1 += sa[t][2] + sa[t][3];
        }
        s0 += __shfl_xor_sync(0xffffffffu, s0, 1);
        s0 += __shfl_xor_sync(0xffffffffu, s0, 2);
        s1 += __shfl_xor_sync(0xffffffffu, s1, 1);
        s1 += __shfl_xor_sync(0xffffffffu, s1, 2);
        l0 = l0 * f0 + s0;
        l1 = l1 * f1 + s1;

        #pragma unroll
        for (int t = 0; t < 16; ++t) {
            oa[t][0] *= f0; oa[t][1] *= f0;
            oa[t][2] *= f1; oa[t][3] *= f1;
        }

        // ---- O += P @ V (P frags built in registers; V via ldmatrix.trans) ----
        #pragma unroll 2
        for (int s = 0; s < 8; ++s) {           // k16 step over kv
            uint32_t ph[4], pl[4];
            split2(sa[2 * s][0],     sa[2 * s][1],     ph[0], pl[0]);
            split2(sa[2 * s][2],     sa[2 * s][3],     ph[1], pl[1]);
            split2(sa[2 * s + 1][0], sa[2 * s + 1][1], ph[2], pl[2]);
            split2(sa[2 * s + 1][2], sa[2 * s + 1][3], ph[3], pl[3]);
            uint32_t vrow = sb + SVHI + (uint32_t)((16 * s + (lane & 15)) * ROWB) + coladd;
            #pragma unroll
            for (int t2 = 0; t2 < 8; ++t2) {    // d16 = two n8 tiles
                uint32_t vhh[4], vll[4];
                uint32_t vaddr = vrow + t2 * 32;
                ldm4t(vhh, vaddr);
                ldm4t(vll, vaddr + (SVLO - SVHI));
                // trans pairing: tile0={r0,r1}, tile1={r2,r3}
                mma16816(oa[2 * t2],     ph, vhh[0], vhh[1]);
                mma16816(oa[2 * t2],     pl, vhh[0], vhh[1]);
                mma16816(oa[2 * t2],     ph, vll[0], vll[1]);
                mma16816(oa[2 * t2 + 1], ph, vhh[2], vhh[3]);
                mma16816(oa[2 * t2 + 1], pl, vhh[2], vhh[3]);
                mma16816(oa[2 * t2 + 1], ph, vll[2], vll[3]);
            }
        }
    }

    // ---- epilogue: O /= l, write out ----
    {
        float i0 = 1.0f / l0, i1 = 1.0f / l1;
        float* o0 = gout + bh_off + (size_t)(qbase + rl0) * HD;
        float* o1 = o0 + 8 * HD;
        #pragma unroll
        for (int t = 0; t < 16; ++t) {
            int c = 8 * t + 2 * (lane & 3);
            *(float2*)(o0 + c) = make_float2(oa[t][0] * i0, oa[t][1] * i0);
            *(float2*)(o1 + c) = make_float2(oa[t][2] * i1, oa[t][3] * i1);
        }
    }
}

extern "C" void kernel_launch(void* const* d_in, const int* in_sizes, int n_in,
                              void* d_out, int out_size)
{
    const float* q = (const float*)d_in[0];
    const float* k = (const float*)d_in[1];
    const float* v = (const float*)d_in[2];
    float* out = (float*)d_out;

    const int seqlen = 2048;
    const int nbh = in_sizes[0] / (seqlen * HD);   // B*H = 32

    cudaFuncSetAttribute(fa_mma_kernel,
                         cudaFuncAttributeMaxDynamicSharedMemorySize, SM_TOTAL);

    dim3 grid(seqlen / BT, nbh);
    fa_mma_kernel<<<grid, 256, SM_TOTAL>>>(q, k, v, out, seqlen);
}

// round 9
// speedup vs baseline: 2.3897x; 1.3224x over previous
#include <cuda_runtime.h>
#include <cuda_bf16.h>
#include <cstdint>

// Causal FlashAttention, fp32 accuracy via split-bf16 mma.sync (HMMA fallback).
// Warp-specialized: 8 consumer warps (MMA+softmax) + 2 producer warps (K/V
// load + bf16-split + STS), 2-stage mbarrier ring over 64-row KV chunks.
// x = hi + lo (bf16 each); x*y ~= hi*hi + hi*lo + lo*hi  (3 MMAs per GEMM).

#define HD 128
#define BT 128                     // q rows per CTA
#define BC 64                      // kv rows per chunk
#define STR 136                    // smem row stride in bf16 elems (272 B)
#define ROWB (STR * 2)             // 272 bytes per row
#define QTILE_B (BT * ROWB)        // 34816 B
#define CTILE_B (BC * ROWB)        // 17408 B per chunk buffer
#define SCALE 0.08838834764831845f // 1/sqrt(128)

// smem map (bytes)
#define MB_FULL0  0
#define MB_FULL1  8
#define MB_EMPTY0 16
#define MB_EMPTY1 24
#define SQHI 1024
#define SQLO (SQHI + QTILE_B)
#define STG0 (SQLO + QTILE_B)          // stage s at STG0 + s*STAGE_B
#define STAGE_B (4 * CTILE_B)          // KHI,KLO,VHI,VLO
#define OFF_KHI 0
#define OFF_KLO CTILE_B
#define OFF_VHI (2 * CTILE_B)
#define OFF_VLO (3 * CTILE_B)
#define SM_TOTAL (STG0 + 2 * STAGE_B)  // 209920 B

__device__ __forceinline__ uint32_t smem_u32(const void* p) {
    uint32_t a;
    asm("{ .reg .u64 t; cvta.to.shared.u64 t, %1; cvt.u32.u64 %0, t; }" : "=r"(a) : "l"(p));
    return a;
}

// split two floats into packed bf16x2 hi + bf16x2 lo (lo = rounded residual)
__device__ __forceinline__ void split2(float f0, float f1, uint32_t& hi, uint32_t& lo) {
    asm("cvt.rn.bf16x2.f32 %0, %1, %2;" : "=r"(hi) : "f"(f1), "f"(f0));
    float h0 = __uint_as_float(hi << 16);
    float h1 = __uint_as_float(hi & 0xFFFF0000u);
    float l0 = f0 - h0, l1 = f1 - h1;
    asm("cvt.rn.bf16x2.f32 %0, %1, %2;" : "=r"(lo) : "f"(l1), "f"(l0));
}

__device__ __forceinline__ void ldm4(uint32_t* r, uint32_t addr) {
    asm volatile("ldmatrix.sync.aligned.m8n8.x4.shared.b16 {%0,%1,%2,%3}, [%4];"
                 : "=r"(r[0]), "=r"(r[1]), "=r"(r[2]), "=r"(r[3]) : "r"(addr));
}
__device__ __forceinline__ void ldm4t(uint32_t* r, uint32_t addr) {
    asm volatile("ldmatrix.sync.aligned.m8n8.x4.trans.shared.b16 {%0,%1,%2,%3}, [%4];"
                 : "=r"(r[0]), "=r"(r[1]), "=r"(r[2]), "=r"(r[3]) : "r"(addr));
}
__device__ __forceinline__ void mma16816(float* c, const uint32_t* a,
                                         uint32_t b0, uint32_t b1) {
    asm volatile("mma.sync.aligned.m16n8k16.row.col.f32.bf16.bf16.f32 "
                 "{%0,%1,%2,%3}, {%4,%5,%6,%7}, {%8,%9}, {%0,%1,%2,%3};"
                 : "+f"(c[0]), "+f"(c[1]), "+f"(c[2]), "+f"(c[3])
                 : "r"(a[0]), "r"(a[1]), "r"(a[2]), "r"(a[3]), "r"(b0), "r"(b1));
}

#define MBAR_INIT(a, n) asm volatile("mbarrier.init.shared.b64 [%0], %1;" :: "r"(a), "r"(n) : "memory")
#define MBAR_ARRIVE(a)  asm volatile("mbarrier.arrive.shared.b64 _, [%0];" :: "r"(a) : "memory")

#define MBAR_WAIT(a, par) do {                                                  \
    uint32_t _m = (a), _p = (par), _d;                                          \
    asm volatile("{\n\t.reg .pred p;\n\t"                                       \
        "mbarrier.try_wait.parity.acquire.cta.shared::cta.b64 p, [%1], %2;\n\t" \
        "selp.b32 %0, 1, 0, p;\n\t}" : "=r"(_d) : "r"(_m), "r"(_p) : "memory"); \
    if (!_d) {                                                                  \
        asm volatile("{\n\t.reg .pred P1;\n\t"                                  \
        "WL_%=:\n\t"                                                            \
        "mbarrier.try_wait.parity.acquire.cta.shared::cta.b64 P1, [%0], %1, 0x989680;\n\t" \
        "@P1 bra.uni WD_%=;\n\t"                                                \
        "bra.uni WL_%=;\n\t"                                                    \
        "WD_%=:\n\t}" :: "r"(_m), "r"(_p) : "memory");                          \
    }                                                                           \
} while (0)

__global__ __launch_bounds__(320, 1)
void fa_ws_kernel(const float* __restrict__ gq,
                  const float* __restrict__ gk,
                  const float* __restrict__ gv,
                  float* __restrict__ gout,
                  int seqlen)
{
    extern __shared__ char smem[];
    const uint32_t sb = smem_u32(smem);
    const int tid = threadIdx.x;
    const int lane = tid & 31;
    const int w = tid >> 5;                         // warps 0-7 consume, 8-9 produce
    const int bh = blockIdx.y;
    const int qtile = gridDim.x - 1 - blockIdx.x;   // heavy tiles first
    const int qbase = qtile * BT;
    const size_t bh_off = (size_t)bh * seqlen * HD;
    const int NC = 2 * qtile + 2;                   // 64-row kv chunks

    if (tid == 0) {
        MBAR_INIT(sb + MB_FULL0, 64);    // 2 producer warps arrive
        MBAR_INIT(sb + MB_FULL1, 64);
        MBAR_INIT(sb + MB_EMPTY0, 256);  // 8 consumer warps arrive
        MBAR_INIT(sb + MB_EMPTY1, 256);
    }

    // ---- Q tile -> smem bf16 hi/lo, scale folded (consumer threads) ----
    if (tid < 256) {
        const float* qp = gq + bh_off + (size_t)qbase * HD;
        #pragma unroll
        for (int it = 0; it < 16; ++it) {
            int idx = tid + it * 256;
            int r = idx >> 5, c4 = idx & 31;
            float4 t = *(const float4*)(qp + (size_t)r * HD + c4 * 4);
            uint32_t h01, l01, h23, l23;
            split2(t.x * SCALE, t.y * SCALE, h01, l01);
            split2(t.z * SCALE, t.w * SCALE, h23, l23);
            uint32_t off = (uint32_t)(r * ROWB + c4 * 8);
            *(uint2*)(smem + SQHI + off) = make_uint2(h01, h23);
            *(uint2*)(smem + SQLO + off) = make_uint2(l01, l23);
        }
    }
    __syncthreads();   // barriers initialized + Q resident

    if (w >= 8) {
        // ================= PRODUCER (2 warps, 64 threads) =================
        const int ptid = tid - 256;     // 0..63
        int eph0 = 0, eph1 = 0;
        for (int jc = 0; jc < NC; ++jc) {
            const int s = jc & 1;
            if (jc >= 2) {
                if (s == 0) { MBAR_WAIT(sb + MB_EMPTY0, eph0); eph0 ^= 1; }
                else        { MBAR_WAIT(sb + MB_EMPTY1, eph1); eph1 ^= 1; }
            }
            const uint32_t stg = (uint32_t)(STG0 + s * STAGE_B);
            const float* kp = gk + bh_off + (size_t)(jc * BC) * HD;
            const float* vp = gv + bh_off + (size_t)(jc * BC) * HD;
            #pragma unroll 4
            for (int it = 0; it < 32; ++it) {
                int idx = ptid + it * 64;           // 0..2047 float4 units
                int r = idx >> 5, c4 = idx & 31;
                uint32_t off = stg + (uint32_t)(r * ROWB + c4 * 8);
                float4 tk = *(const float4*)(kp + (size_t)r * HD + c4 * 4);
                uint32_t h01, l01, h23, l23;
                split2(tk.x, tk.y, h01, l01);
                split2(tk.z, tk.w, h23, l23);
                *(uint2*)(smem + off + OFF_KHI) = make_uint2(h01, h23);
                *(uint2*)(smem + off + OFF_KLO) = make_uint2(l01, l23);
                float4 tv = *(const float4*)(vp + (size_t)r * HD + c4 * 4);
                split2(tv.x, tv.y, h01, l01);
                split2(tv.z, tv.w, h23, l23);
                *(uint2*)(smem + off + OFF_VHI) = make_uint2(h01, h23);
                *(uint2*)(smem + off + OFF_VLO) = make_uint2(l01, l23);
            }
            MBAR_ARRIVE(sb + (s ? MB_FULL1 : MB_FULL0));
        }
        return;
    }

    // ================= CONSUMER (8 warps, 256 threads) =================
    const int rl0 = 16 * w + (lane >> 2);               // local row (low half)
    const uint32_t coladd = (lane & 16) ? 16u : 0u;     // +8 elems = 16 B
    const uint32_t arow_off = (uint32_t)((16 * w + (lane & 15)) * ROWB) + coladd;
    const uint32_t brow_off = (uint32_t)((lane & 15) * ROWB) + coladd;
    const int gr0 = qbase + rl0, gr1 = gr0 + 8;

    float m0 = -1e30f, m1 = -1e30f, l0 = 0.0f, l1 = 0.0f;
    float oa[16][4];
    #pragma unroll
    for (int t = 0; t < 16; ++t)
        #pragma unroll
        for (int e = 0; e < 4; ++e) oa[t][e] = 0.0f;

    int fph0 = 0, fph1 = 0;
    for (int jc = 0; jc < NC; ++jc) {
        const int s = jc & 1;
        if (s == 0) { MBAR_WAIT(sb + MB_FULL0, fph0); fph0 ^= 1; }
        else        { MBAR_WAIT(sb + MB_FULL1, fph1); fph1 ^= 1; }
        const uint32_t stg = sb + (uint32_t)(STG0 + s * STAGE_B);

        // ---- S = Q @ K^T over 64 kv cols (split-bf16, 3 MMAs) ----
        float sa[8][4];
        #pragma unroll
        for (int t = 0; t < 8; ++t)
            #pragma unroll
            for (int e = 0; e < 4; ++e) sa[t][e] = 0.0f;

        #pragma unroll 2
        for (int s8 = 0; s8 < 8; ++s8) {        // k16 over d
            uint32_t ah[4], al[4];
            ldm4(ah, sb + SQHI + arow_off + s8 * 32);
            ldm4(al, sb + SQLO + arow_off + s8 * 32);
            #pragma unroll
            for (int t2 = 0; t2 < 4; ++t2) {    // n16 = two n8 tiles
                uint32_t bhh[4], bll[4];
                uint32_t baddr = stg + OFF_KHI + (uint32_t)(t2 * 16 * ROWB) + brow_off + s8 * 32;
                ldm4(bhh, baddr);
                ldm4(bll, baddr + (OFF_KLO - OFF_KHI));
                mma16816(sa[2 * t2],     ah, bhh[0], bhh[2]);
                mma16816(sa[2 * t2],     ah, bll[0], bll[2]);
                mma16816(sa[2 * t2],     al, bhh[0], bhh[2]);
                mma16816(sa[2 * t2 + 1], ah, bhh[1], bhh[3]);
                mma16816(sa[2 * t2 + 1], ah, bll[1], bll[3]);
                mma16816(sa[2 * t2 + 1], al, bhh[1], bhh[3]);
            }
        }

        // ---- causal mask (only the last two chunks touch the diagonal) ----
        if (jc >= 2 * qtile) {
            const int colbase = jc * BC + 2 * (lane & 3);
            #pragma unroll
            for (int t = 0; t < 8; ++t) {
                int c = colbase + 8 * t;
                if (c     > gr0) sa[t][0] = -1e30f;
                if (c + 1 > gr0) sa[t][1] = -1e30f;
                if (c     > gr1) sa[t][2] = -1e30f;
                if (c + 1 > gr1) sa[t][3] = -1e30f;
            }
        }

        // ---- online softmax (two rows per thread; reduce over 4 lanes) ----
        float mx0 = -1e30f, mx1 = -1e30f;
        #pragma unroll
        for (int t = 0; t < 8; ++t) {
            mx0 = fmaxf(mx0, fmaxf(sa[t][0], sa[t][1]));
            mx1 = fmaxf(mx1, fmaxf(sa[t][2], sa[t][3]));
        }
        mx0 = fmaxf(mx0, __shfl_xor_sync(0xffffffffu, mx0, 1));
        mx0 = fmaxf(mx0, __shfl_xor_sync(0xffffffffu, mx0, 2));
        mx1 = fmaxf(mx1, __shfl_xor_sync(0xffffffffu, mx1, 1));
        mx1 = fmaxf(mx1, __shfl_xor_sync(0xffffffffu, mx1, 2));

        float mn0 = fmaxf(m0, mx0), mn1 = fmaxf(m1, mx1);
        float f0 = __expf(m0 - mn0), f1 = __expf(m1 - mn1);
        m0 = mn0; m1 = mn1;

        float s0 = 0.0f, s1 = 0.0f;
        #pragma unroll
        for (int t = 0; t < 8; ++t) {
            sa[t][0] = __expf(sa[t][0] - mn0);
            sa[t][1] = __expf(sa[t][1] - mn0);
            sa[t][2] = __expf(sa[t][2] - mn1);
            sa[t][3] = __expf(sa[t][3] - mn1);
            s0 += sa[t][0] + sa[t][1];
            s1 += sa[t][2] + sa[t][3];
        }
        s0 += __shfl_xor_sync(0xffffffffu, s0, 1);
        s0 += __shfl_xor_sync(0xffffffffu, s0, 2);
        s1 += __shfl_xor_sync(0xffffffffu, s1, 1);
        s1 += __shfl_xor_sync(0xffffffffu, s1, 2);
        l0 = l0 * f0 + s0;
        l1 = l1 * f1 + s1;

        #pragma unroll
        for (int t = 0; t < 16; ++t) {
            oa[t][0] *= f0; oa[t][1] *= f0;
            oa[t][2] *= f1; oa[t][3] *= f1;
        }

        // ---- O += P @ V (P frags in regs; V via ldmatrix.trans) ----
        #pragma unroll 2
        for (int s4 = 0; s4 < 4; ++s4) {        // k16 over kv
            uint32_t ph[4], pl[4];
            split2(sa[2 * s4][0],     sa[2 * s4][1],     ph[0], pl[0]);
            split2(sa[2 * s4][2],     sa[2 * s4][3],     ph[1], pl[1]);
            split2(sa[2 * s4 + 1][0], sa[2 * s4 + 1][1], ph[2], pl[2]);
            split2(sa[2 * s4 + 1][2], sa[2 * s4 + 1][3], ph[3], pl[3]);
            uint32_t vrow = stg + OFF_VHI + (uint32_t)((16 * s4 + (lane & 15)) * ROWB) + coladd;
            #pragma unroll
            for (int t2 = 0; t2 < 8; ++t2) {    // d16 = two n8 tiles
                uint32_t vhh[4], vll[4];
                uint32_t vaddr = vrow + t2 * 32;
                ldm4t(vhh, vaddr);
                ldm4t(vll, vaddr + (OFF_VLO - OFF_VHI));
                mma16816(oa[2 * t2],     ph, vhh[0], vhh[1]);
                mma16816(oa[2 * t2],     pl, vhh[0], vhh[1]);
                mma16816(oa[2 * t2],     ph, vll[0], vll[1]);
                mma16816(oa[2 * t2 + 1], ph, vhh[2], vhh[3]);
                mma16816(oa[2 * t2 + 1], pl, vhh[2], vhh[3]);
                mma16816(oa[2 * t2 + 1], ph, vll[2], vll[3]);
            }
        }

        MBAR_ARRIVE(sb + (s ? MB_EMPTY1 : MB_EMPTY0));
    }

    // ---- epilogue: O /= l, write out ----
    {
        float i0 = 1.0f / l0, i1 = 1.0f / l1;
        float* o0 = gout + bh_off + (size_t)(qbase + rl0) * HD;
        float* o1 = o0 + 8 * HD;
        #pragma unroll
        for (int t = 0; t < 16; ++t) {
            int c = 8 * t + 2 * (lane & 3);
            *(float2*)(o0 + c) = make_float2(oa[t][0] * i0, oa[t][1] * i0);
            *(float2*)(o1 + c) = make_float2(oa[t][2] * i1, oa[t][3] * i1);
        }
    }
}

extern "C" void kernel_launch(void* const* d_in, const int* in_sizes, int n_in,
                              void* d_out, int out_size)
{
    const float* q = (const float*)d_in[0];
    const float* k = (const float*)d_in[1];
    const float* v = (const float*)d_in[2];
    float* out = (float*)d_out;

    const int seqlen = 2048;
    const int nbh = in_sizes[0] / (seqlen * HD);   // B*H = 32

    cudaFuncSetAttribute(fa_ws_kernel,
                         cudaFuncAttributeMaxDynamicSharedMemorySize, SM_TOTAL);

    dim3 grid(seqlen / BT, nbh);
    fa_ws_kernel<<<grid, 320, SM_TOTAL>>>(q, k, v, out, seqlen);
}

// round 10
// speedup vs baseline: 2.4520x; 1.0261x over previous
#include <cuda_runtime.h>
#include <cuda_bf16.h>
#include <cstdint>

// Causal FlashAttention, fp32 accuracy via split-bf16 mma.sync (HMMA fallback).
// Warp-specialized: 8 consumer warps (MMA+softmax) + 2 producer warps (K/V
// load + bf16-split + STS), 2-stage mbarrier ring over 64-row KV chunks.
// R9: b-fragments preloaded per k-step and MMAs issued term-major so no two
// consecutive MMAs share an accumulator (kills RAW serialization).

#define HD 128
#define BT 128                     // q rows per CTA
#define BC 64                      // kv rows per chunk
#define STR 136                    // smem row stride in bf16 elems (272 B)
#define ROWB (STR * 2)             // 272 bytes per row
#define QTILE_B (BT * ROWB)        // 34816 B
#define CTILE_B (BC * ROWB)        // 17408 B per chunk buffer
#define SCALE 0.08838834764831845f // 1/sqrt(128)

// smem map (bytes)
#define MB_FULL0  0
#define MB_FULL1  8
#define MB_EMPTY0 16
#define MB_EMPTY1 24
#define SQHI 1024
#define SQLO (SQHI + QTILE_B)
#define STG0 (SQLO + QTILE_B)          // stage s at STG0 + s*STAGE_B
#define STAGE_B (4 * CTILE_B)          // KHI,KLO,VHI,VLO
#define OFF_KHI 0
#define OFF_KLO CTILE_B
#define OFF_VHI (2 * CTILE_B)
#define OFF_VLO (3 * CTILE_B)
#define SM_TOTAL (STG0 + 2 * STAGE_B)  // 209920 B

__device__ __forceinline__ uint32_t smem_u32(const void* p) {
    uint32_t a;
    asm("{ .reg .u64 t; cvta.to.shared.u64 t, %1; cvt.u32.u64 %0, t; }" : "=r"(a) : "l"(p));
    return a;
}

// split two floats into packed bf16x2 hi + bf16x2 lo (lo = rounded residual)
__device__ __forceinline__ void split2(float f0, float f1, uint32_t& hi, uint32_t& lo) {
    asm("cvt.rn.bf16x2.f32 %0, %1, %2;" : "=r"(hi) : "f"(f1), "f"(f0));
    float h0 = __uint_as_float(hi << 16);
    float h1 = __uint_as_float(hi & 0xFFFF0000u);
    float l0 = f0 - h0, l1 = f1 - h1;
    asm("cvt.rn.bf16x2.f32 %0, %1, %2;" : "=r"(lo) : "f"(l1), "f"(l0));
}

__device__ __forceinline__ void ldm4(uint32_t* r, uint32_t addr) {
    asm volatile("ldmatrix.sync.aligned.m8n8.x4.shared.b16 {%0,%1,%2,%3}, [%4];"
                 : "=r"(r[0]), "=r"(r[1]), "=r"(r[2]), "=r"(r[3]) : "r"(addr));
}
__device__ __forceinline__ void ldm4t(uint32_t* r, uint32_t addr) {
    asm volatile("ldmatrix.sync.aligned.m8n8.x4.trans.shared.b16 {%0,%1,%2,%3}, [%4];"
                 : "=r"(r[0]), "=r"(r[1]), "=r"(r[2]), "=r"(r[3]) : "r"(addr));
}
__device__ __forceinline__ void mma16816(float* c, const uint32_t* a,
                                         uint32_t b0, uint32_t b1) {
    asm volatile("mma.sync.aligned.m16n8k16.row.col.f32.bf16.bf16.f32 "
                 "{%0,%1,%2,%3}, {%4,%5,%6,%7}, {%8,%9}, {%0,%1,%2,%3};"
                 : "+f"(c[0]), "+f"(c[1]), "+f"(c[2]), "+f"(c[3])
                 : "r"(a[0]), "r"(a[1]), "r"(a[2]), "r"(a[3]), "r"(b0), "r"(b1));
}

#define MBAR_INIT(a, n) asm volatile("mbarrier.init.shared.b64 [%0], %1;" :: "r"(a), "r"(n) : "memory")
#define MBAR_ARRIVE(a)  asm volatile("mbarrier.arrive.shared.b64 _, [%0];" :: "r"(a) : "memory")

#define MBAR_WAIT(a, par) do {                                                  \
    uint32_t _m = (a), _p = (par), _d;                                          \
    asm volatile("{\n\t.reg .pred p;\n\t"                                       \
        "mbarrier.try_wait.parity.acquire.cta.shared::cta.b64 p, [%1], %2;\n\t" \
        "selp.b32 %0, 1, 0, p;\n\t}" : "=r"(_d) : "r"(_m), "r"(_p) : "memory"); \
    if (!_d) {                                                                  \
        asm volatile("{\n\t.reg .pred P1;\n\t"                                  \
        "WL_%=:\n\t"                                                            \
        "mbarrier.try_wait.parity.acquire.cta.shared::cta.b64 P1, [%0], %1, 0x989680;\n\t" \
        "@P1 bra.uni WD_%=;\n\t"                                                \
        "bra.uni WL_%=;\n\t"                                                    \
        "WD_%=:\n\t}" :: "r"(_m), "r"(_p) : "memory");                          \
    }                                                                           \
} while (0)

__global__ __launch_bounds__(320, 1)
void fa_ws_kernel(const float* __restrict__ gq,
                  const float* __restrict__ gk,
                  const float* __restrict__ gv,
                  float* __restrict__ gout,
                  int seqlen)
{
    extern __shared__ char smem[];
    const uint32_t sb = smem_u32(smem);
    const int tid = threadIdx.x;
    const int lane = tid & 31;
    const int w = tid >> 5;                         // warps 0-7 consume, 8-9 produce
    const int bh = blockIdx.y;
    const int qtile = gridDim.x - 1 - blockIdx.x;   // heavy tiles first
    const int qbase = qtile * BT;
    const size_t bh_off = (size_t)bh * seqlen * HD;
    const int NC = 2 * qtile + 2;                   // 64-row kv chunks

    if (tid == 0) {
        MBAR_INIT(sb + MB_FULL0, 64);    // 2 producer warps arrive
        MBAR_INIT(sb + MB_FULL1, 64);
        MBAR_INIT(sb + MB_EMPTY0, 256);  // 8 consumer warps arrive
        MBAR_INIT(sb + MB_EMPTY1, 256);
    }

    // ---- Q tile -> smem bf16 hi/lo, scale folded (consumer threads) ----
    if (tid < 256) {
        const float* qp = gq + bh_off + (size_t)qbase * HD;
        #pragma unroll
        for (int it = 0; it < 16; ++it) {
            int idx = tid + it * 256;
            int r = idx >> 5, c4 = idx & 31;
            float4 t = *(const float4*)(qp + (size_t)r * HD + c4 * 4);
            uint32_t h01, l01, h23, l23;
            split2(t.x * SCALE, t.y * SCALE, h01, l01);
            split2(t.z * SCALE, t.w * SCALE, h23, l23);
            uint32_t off = (uint32_t)(r * ROWB + c4 * 8);
            *(uint2*)(smem + SQHI + off) = make_uint2(h01, h23);
            *(uint2*)(smem + SQLO + off) = make_uint2(l01, l23);
        }
    }
    __syncthreads();   // barriers initialized + Q resident

    if (w >= 8) {
        // ================= PRODUCER (2 warps, 64 threads) =================
        const int ptid = tid - 256;     // 0..63
        int eph0 = 0, eph1 = 0;
        for (int jc = 0; jc < NC; ++jc) {
            const int s = jc & 1;
            if (jc >= 2) {
                if (s == 0) { MBAR_WAIT(sb + MB_EMPTY0, eph0); eph0 ^= 1; }
                else        { MBAR_WAIT(sb + MB_EMPTY1, eph1); eph1 ^= 1; }
            }
            const uint32_t stg = (uint32_t)(STG0 + s * STAGE_B);
            const float* kp = gk + bh_off + (size_t)(jc * BC) * HD;
            const float* vp = gv + bh_off + (size_t)(jc * BC) * HD;
            #pragma unroll 4
            for (int it = 0; it < 32; ++it) {
                int idx = ptid + it * 64;           // 0..2047 float4 units
                int r = idx >> 5, c4 = idx & 31;
                uint32_t off = stg + (uint32_t)(r * ROWB + c4 * 8);
                float4 tk = *(const float4*)(kp + (size_t)r * HD + c4 * 4);
                uint32_t h01, l01, h23, l23;
                split2(tk.x, tk.y, h01, l01);
                split2(tk.z, tk.w, h23, l23);
                *(uint2*)(smem + off + OFF_KHI) = make_uint2(h01, h23);
                *(uint2*)(smem + off + OFF_KLO) = make_uint2(l01, l23);
                float4 tv = *(const float4*)(vp + (size_t)r * HD + c4 * 4);
                split2(tv.x, tv.y, h01, l01);
                split2(tv.z, tv.w, h23, l23);
                *(uint2*)(smem + off + OFF_VHI) = make_uint2(h01, h23);
                *(uint2*)(smem + off + OFF_VLO) = make_uint2(l01, l23);
            }
            MBAR_ARRIVE(sb + (s ? MB_FULL1 : MB_FULL0));
        }
        return;
    }

    // ================= CONSUMER (8 warps, 256 threads) =================
    const int rl0 = 16 * w + (lane >> 2);               // local row (low half)
    const uint32_t coladd = (lane & 16) ? 16u : 0u;     // +8 elems = 16 B
    const uint32_t arow_off = (uint32_t)((16 * w + (lane & 15)) * ROWB) + coladd;
    const uint32_t brow_off = (uint32_t)((lane & 15) * ROWB) + coladd;
    const int gr0 = qbase + rl0, gr1 = gr0 + 8;

    float m0 = -1e30f, m1 = -1e30f, l0 = 0.0f, l1 = 0.0f;
    float oa[16][4];
    #pragma unroll
    for (int t = 0; t < 16; ++t)
        #pragma unroll
        for (int e = 0; e < 4; ++e) oa[t][e] = 0.0f;

    int fph0 = 0, fph1 = 0;
    for (int jc = 0; jc < NC; ++jc) {
        const int s = jc & 1;
        if (s == 0) { MBAR_WAIT(sb + MB_FULL0, fph0); fph0 ^= 1; }
        else        { MBAR_WAIT(sb + MB_FULL1, fph1); fph1 ^= 1; }
        const uint32_t stg = sb + (uint32_t)(STG0 + s * STAGE_B);

        // ---- S = Q @ K^T over 64 kv cols (split-bf16, 3 MMAs) ----
        float sa[8][4];
        #pragma unroll
        for (int t = 0; t < 8; ++t)
            #pragma unroll
            for (int e = 0; e < 4; ++e) sa[t][e] = 0.0f;

        #pragma unroll 2
        for (int s8 = 0; s8 < 8; ++s8) {        // k16 over d
            uint32_t ah[4], al[4];
            ldm4(ah, sb + SQHI + arow_off + s8 * 32);
            ldm4(al, sb + SQLO + arow_off + s8 * 32);
            // preload all b-frags for this k-step (hi+lo, 4 n16 tiles)
            uint32_t bhh[4][4], bll[4][4];
            #pragma unroll
            for (int t2 = 0; t2 < 4; ++t2) {
                uint32_t baddr = stg + OFF_KHI + (uint32_t)(t2 * 16 * ROWB) + brow_off + s8 * 32;
                ldm4(bhh[t2], baddr);
                ldm4(bll[t2], baddr + (OFF_KLO - OFF_KHI));
            }
            // term-major issue: consecutive MMAs never share an accumulator
            #pragma unroll
            for (int t2 = 0; t2 < 4; ++t2) {
                mma16816(sa[2 * t2],     ah, bhh[t2][0], bhh[t2][2]);
                mma16816(sa[2 * t2 + 1], ah, bhh[t2][1], bhh[t2][3]);
            }
            #pragma unroll
            for (int t2 = 0; t2 < 4; ++t2) {
                mma16816(sa[2 * t2],     ah, bll[t2][0], bll[t2][2]);
                mma16816(sa[2 * t2 + 1], ah, bll[t2][1], bll[t2][3]);
            }
            #pragma unroll
            for (int t2 = 0; t2 < 4; ++t2) {
                mma16816(sa[2 * t2],     al, bhh[t2][0], bhh[t2][2]);
                mma16816(sa[2 * t2 + 1], al, bhh[t2][1], bhh[t2][3]);
            }
        }

        // ---- causal mask (only the last two chunks touch the diagonal) ----
        if (jc >= 2 * qtile) {
            const int colbase = jc * BC + 2 * (lane & 3);
            #pragma unroll
            for (int t = 0; t < 8; ++t) {
                int c = colbase + 8 * t;
                if (c     > gr0) sa[t][0] = -1e30f;
                if (c + 1 > gr0) sa[t][1] = -1e30f;
                if (c     > gr1) sa[t][2] = -1e30f;
                if (c + 1 > gr1) sa[t][3] = -1e30f;
            }
        }

        // ---- online softmax (two rows per thread; reduce over 4 lanes) ----
        float mx0 = -1e30f, mx1 = -1e30f;
        #pragma unroll
        for (int t = 0; t < 8; ++t) {
            mx0 = fmaxf(mx0, fmaxf(sa[t][0], sa[t][1]));
            mx1 = fmaxf(mx1, fmaxf(sa[t][2], sa[t][3]));
        }
        mx0 = fmaxf(mx0, __shfl_xor_sync(0xffffffffu, mx0, 1));
        mx0 = fmaxf(mx0, __shfl_xor_sync(0xffffffffu, mx0, 2));
        mx1 = fmaxf(mx1, __shfl_xor_sync(0xffffffffu, mx1, 1));
        mx1 = fmaxf(mx1, __shfl_xor_sync(0xffffffffu, mx1, 2));

        float mn0 = fmaxf(m0, mx0), mn1 = fmaxf(m1, mx1);
        float f0 = __expf(m0 - mn0), f1 = __expf(m1 - mn1);
        m0 = mn0; m1 = mn1;

        float s0 = 0.0f, s1 = 0.0f;
        #pragma unroll
        for (int t = 0; t < 8; ++t) {
            sa[t][0] = __expf(sa[t][0] - mn0);
            sa[t][1] = __expf(sa[t][1] - mn0);
            sa[t][2] = __expf(sa[t][2] - mn1);
            sa[t][3] = __expf(sa[t][3] - mn1);
            s0 += sa[t][0] + sa[t][1];
            s1 += sa[t][2] + sa[t][3];
        }
        s0 += __shfl_xor_sync(0xffffffffu, s0, 1);
        s0 += __shfl_xor_sync(0xffffffffu, s0, 2);
        s1 += __shfl_xor_sync(0xffffffffu, s1, 1);
        s1 += __shfl_xor_sync(0xffffffffu, s1, 2);
        l0 = l0 * f0 + s0;
        l1 = l1 * f1 + s1;

        #pragma unroll
        for (int t = 0; t < 16; ++t) {
            oa[t][0] *= f0; oa[t][1] *= f0;
            oa[t][2] *= f1; oa[t][3] *= f1;
        }

        // ---- O += P @ V (P frags in regs; V via ldmatrix.trans) ----
        #pragma unroll 2
        for (int s4 = 0; s4 < 4; ++s4) {        // k16 over kv
            uint32_t ph[4], pl[4];
            split2(sa[2 * s4][0],     sa[2 * s4][1],     ph[0], pl[0]);
            split2(sa[2 * s4][2],     sa[2 * s4][3],     ph[1], pl[1]);
            split2(sa[2 * s4 + 1][0], sa[2 * s4 + 1][1], ph[2], pl[2]);
            split2(sa[2 * s4 + 1][2], sa[2 * s4 + 1][3], ph[3], pl[3]);
            uint32_t vrow = stg + OFF_VHI + (uint32_t)((16 * s4 + (lane & 15)) * ROWB) + coladd;
            // two halves of 4 d16-tiles each: preload V frags, term-major MMAs
            #pragma unroll
            for (int half = 0; half < 2; ++half) {
                uint32_t vhh[4][4], vll[4][4];
                #pragma unroll
                for (int q4 = 0; q4 < 4; ++q4) {
                    uint32_t vaddr = vrow + (half * 4 + q4) * 32;
                    ldm4t(vhh[q4], vaddr);
                    ldm4t(vll[q4], vaddr + (OFF_VLO - OFF_VHI));
                }
                #pragma unroll
                for (int q4 = 0; q4 < 4; ++q4) {
                    int t2 = half * 4 + q4;
                    mma16816(oa[2 * t2],     ph, vhh[q4][0], vhh[q4][1]);
                    mma16816(oa[2 * t2 + 1], ph, vhh[q4][2], vhh[q4][3]);
                }
                #pragma unroll
                for (int q4 = 0; q4 < 4; ++q4) {
                    int t2 = half * 4 + q4;
                    mma16816(oa[2 * t2],     pl, vhh[q4][0], vhh[q4][1]);
                    mma16816(oa[2 * t2 + 1], pl, vhh[q4][2], vhh[q4][3]);
                }
                #pragma unroll
                for (int q4 = 0; q4 < 4; ++q4) {
                    int t2 = half * 4 + q4;
                    mma16816(oa[2 * t2],     ph, vll[q4][0], vll[q4][1]);
                    mma16816(oa[2 * t2 + 1], ph, vll[q4][2], vll[q4][3]);
                }
            }
        }

        MBAR_ARRIVE(sb + (s ? MB_EMPTY1 : MB_EMPTY0));
    }

    // ---- epilogue: O /= l, write out ----
    {
        float i0 = 1.0f / l0, i1 = 1.0f / l1;
        float* o0 = gout + bh_off + (size_t)(qbase + rl0) * HD;
        float* o1 = o0 + 8 * HD;
        #pragma unroll
        for (int t = 0; t < 16; ++t) {
            int c = 8 * t + 2 * (lane & 3);
            *(float2*)(o0 + c) = make_float2(oa[t][0] * i0, oa[t][1] * i0);
            *(float2*)(o1 + c) = make_float2(oa[t][2] * i1, oa[t][3] * i1);
        }
    }
}

extern "C" void kernel_launch(void* const* d_in, const int* in_sizes, int n_in,
                              void* d_out, int out_size)
{
    const float* q = (const float*)d_in[0];
    const float* k = (const float*)d_in[1];
    const float* v = (const float*)d_in[2];
    float* out = (float*)d_out;

    const int seqlen = 2048;
    const int nbh = in_sizes[0] / (seqlen * HD);   // B*H = 32

    cudaFuncSetAttribute(fa_ws_kernel,
                         cudaFuncAttributeMaxDynamicSharedMemorySize, SM_TOTAL);

    dim3 grid(seqlen / BT, nbh);
    fa_ws_kernel<<<grid, 320, SM_TOTAL>>>(q, k, v, out, seqlen);
}